// round 7
// baseline (speedup 1.0000x reference)
#include <cuda_runtime.h>
#include <cuda_bf16.h>
#include <cstdint>
#include <math.h>

#define N      2048
#define NN     (N * N)
#define NF     8
#define NCOEF  17          // order = 16 (fixed by setup_inputs)

// fp32 Chebyshev slices T_0..T_16 (recurrence epilogue + final combine)
__device__ float d_T[NCOEF * NN];
__device__ float d_c[NCOEF * NF];
// bf16 hi/lo split operands. A = L (row-major). B = T_j splits (row-major;
// T_j is symmetric, so row-major == its transpose). Double-buffered by j&1:
// GEMM k reads buf (k-1)&1, writes buf k&1.
__device__ __nv_bfloat16 d_Ahi[NN], d_Alo[NN];
__device__ __nv_bfloat16 d_Bhi[2][NN], d_Blo[2][NN];

// ---------------------------------------------------------------------------
// Warp-level MMA helpers (portable PTX, valid on plain sm_103 target)
// ---------------------------------------------------------------------------
__device__ __forceinline__ uint32_t smem_u32(const void* p) {
    return (uint32_t)__cvta_generic_to_shared(p);
}
__device__ __forceinline__ void ldsm_x4(uint32_t* r, uint32_t a) {
    asm volatile("ldmatrix.sync.aligned.m8n8.x4.shared.b16 {%0,%1,%2,%3}, [%4];"
                 : "=r"(r[0]), "=r"(r[1]), "=r"(r[2]), "=r"(r[3]) : "r"(a));
}
__device__ __forceinline__ void ldsm_x2(uint32_t* r, uint32_t a) {
    asm volatile("ldmatrix.sync.aligned.m8n8.x2.shared.b16 {%0,%1}, [%2];"
                 : "=r"(r[0]), "=r"(r[1]) : "r"(a));
}
__device__ __forceinline__ void mma_bf16(float* c, const uint32_t* a,
                                         const uint32_t* b) {
    asm volatile(
        "mma.sync.aligned.m16n8k16.row.col.f32.bf16.bf16.f32 "
        "{%0,%1,%2,%3}, {%4,%5,%6,%7}, {%8,%9}, {%0,%1,%2,%3};"
        : "+f"(c[0]), "+f"(c[1]), "+f"(c[2]), "+f"(c[3])
        : "r"(a[0]), "r"(a[1]), "r"(a[2]), "r"(a[3]), "r"(b[0]), "r"(b[1]));
}

// ---------------------------------------------------------------------------
// Chebyshev coefficients: c = (2/Ncoef) * C @ fe    (a1 = a2 = 1)
// ---------------------------------------------------------------------------
__global__ void coeff_kernel(const float* __restrict__ taus) {
    int j = threadIdx.x;
    if (j >= NCOEF) return;
    double acc[NF];
#pragma unroll
    for (int f = 0; f < NF; f++) acc[f] = 0.0;
    for (int n = 0; n < NCOEF; n++) {
        double ang = M_PI * (n + 0.5) / NCOEF;
        double pt  = cos(ang) + 1.0;
        double Cjn = cos((double)j * ang);
#pragma unroll
        for (int f = 0; f < NF; f++)
            acc[f] += Cjn * exp(-pt * (double)taus[f]);
    }
#pragma unroll
    for (int f = 0; f < NF; f++)
        d_c[j * NF + f] = (float)(acc[f] * 2.0 / NCOEF);
}

// ---------------------------------------------------------------------------
// T0 = I, T1 = L - I (fp32); A-splits of L; B-splits of T1 into buf 1
// ---------------------------------------------------------------------------
__global__ void init_kernel(const float* __restrict__ L) {
    int idx = blockIdx.x * blockDim.x + threadIdx.x;
    if (idx >= NN) return;
    int i = idx >> 11;
    int j = idx & (N - 1);
    float e = (i == j) ? 1.0f : 0.0f;
    float v = L[idx];
    float t1 = v - e;
    d_T[idx]      = e;
    d_T[NN + idx] = t1;
    __nv_bfloat16 h = __float2bfloat16(v);
    d_Ahi[idx] = h;
    d_Alo[idx] = __float2bfloat16(v - __bfloat162float(h));
    __nv_bfloat16 h1 = __float2bfloat16(t1);
    d_Bhi[1][idx] = h1;
    d_Blo[1][idx] = __float2bfloat16(t1 - __bfloat162float(h1));
}

// ---------------------------------------------------------------------------
// HMMA GEMM: T_k = 2*(L @ T_{k-1}) - 2*T_{k-1} - T_{k-2}
// CTA 128x128, BK=32, 256 threads = 8 warps (2m x 4n), warp tile 64x32.
// bf16 split-3, fp32 accumulate. Epilogue emits bf16 splits of T_k.
// ---------------------------------------------------------------------------
#define BK    32
#define PADK  40                      // row stride in elements (80 B)
#define NKT   (N / BK)                // 64

__global__ __launch_bounds__(256, 2)
void mma_gemm(int k) {
    __shared__ __align__(16) __nv_bfloat16 sAhi[128 * PADK];
    __shared__ __align__(16) __nv_bfloat16 sAlo[128 * PADK];
    __shared__ __align__(16) __nv_bfloat16 sBhi[128 * PADK];
    __shared__ __align__(16) __nv_bfloat16 sBlo[128 * PADK];

    const float* __restrict__ Bcur = d_T + (size_t)(k - 1) * NN;
    const float* __restrict__ Bold = d_T + (size_t)(k - 2) * NN;
    float* __restrict__ Cnew       = d_T + (size_t)k * NN;
    int rbuf = (k - 1) & 1, wbuf = k & 1;

    int tid  = threadIdx.x;
    int lane = tid & 31, wid = tid >> 5;
    int wm = wid & 1, wn = wid >> 1;         // warp grid 2(m) x 4(n)
    int g = lane >> 2, tig = lane & 3;
    int quad = lane >> 3, lr = lane & 7;

    int m0 = blockIdx.y * 128, n0 = blockIdx.x * 128;

    const __nv_bfloat16* gAh = d_Ahi + (size_t)m0 * N;
    const __nv_bfloat16* gAl = d_Alo + (size_t)m0 * N;
    const __nv_bfloat16* gBh = d_Bhi[rbuf] + (size_t)n0 * N;
    const __nv_bfloat16* gBl = d_Blo[rbuf] + (size_t)n0 * N;

    uint32_t uAhi = smem_u32(sAhi), uAlo = smem_u32(sAlo);
    uint32_t uBhi = smem_u32(sBhi), uBlo = smem_u32(sBlo);

    // ldmatrix per-thread byte offsets (within a tile array)
    uint32_t aoff[4], boff[4];
#pragma unroll
    for (int i = 0; i < 4; ++i)
        aoff[i] = (uint32_t)((wm * 64 + i * 16 + lr + (quad & 1) * 8) * (PADK * 2)
                             + (quad >> 1) * 16);
#pragma unroll
    for (int j = 0; j < 4; ++j)
        boff[j] = (uint32_t)((wn * 32 + j * 8 + lr) * (PADK * 2)
                             + ((lane >> 3) & 1) * 16);

    float acc[4][4][4];
#pragma unroll
    for (int i = 0; i < 4; ++i)
#pragma unroll
        for (int j = 0; j < 4; ++j)
#pragma unroll
            for (int c = 0; c < 4; ++c) acc[i][j][c] = 0.0f;

    for (int kt = 0; kt < NKT; ++kt) {
        int k0 = kt * BK;
        // Load 128x32 bf16 tiles (4 arrays), 2 x uint4 per thread per array
#pragma unroll
        for (int h = 0; h < 2; ++h) {
            int f = tid + h * 256;          // 0..511
            int r = f >> 2, c4 = f & 3;     // row, 16B chunk
            uint32_t so = (uint32_t)(r * (PADK * 2) + c4 * 16);
            const uint4* pa = (const uint4*)(gAh + (size_t)r * N + k0) + c4;
            const uint4* pb = (const uint4*)(gAl + (size_t)r * N + k0) + c4;
            const uint4* pc = (const uint4*)(gBh + (size_t)r * N + k0) + c4;
            const uint4* pd = (const uint4*)(gBl + (size_t)r * N + k0) + c4;
            *(uint4*)((char*)sAhi + so) = *pa;
            *(uint4*)((char*)sAlo + so) = *pb;
            *(uint4*)((char*)sBhi + so) = *pc;
            *(uint4*)((char*)sBlo + so) = *pd;
        }
        __syncthreads();

#pragma unroll
        for (int s = 0; s < 2; ++s) {       // two K=16 steps within BK=32
            uint32_t soff = s * 32;
            uint32_t bh[4][2], bl[4][2];
#pragma unroll
            for (int j = 0; j < 4; ++j) {
                ldsm_x2(bh[j], uBhi + boff[j] + soff);
                ldsm_x2(bl[j], uBlo + boff[j] + soff);
            }
#pragma unroll
            for (int i = 0; i < 4; ++i) {
                uint32_t ah[4], al[4];
                ldsm_x4(ah, uAhi + aoff[i] + soff);
                ldsm_x4(al, uAlo + aoff[i] + soff);
#pragma unroll
                for (int j = 0; j < 4; ++j) {
                    mma_bf16(acc[i][j], ah, bh[j]);
                    mma_bf16(acc[i][j], ah, bl[j]);
                    mma_bf16(acc[i][j], al, bh[j]);
                }
            }
        }
        __syncthreads();
    }

    // Epilogue: T_k = 2*acc - 2*T_{k-1} - T_{k-2}; emit bf16 splits of T_k
    bool emit = (k < NCOEF - 1);
    __nv_bfloat16* bh = d_Bhi[wbuf];
    __nv_bfloat16* bl = d_Blo[wbuf];
#pragma unroll
    for (int i = 0; i < 4; ++i) {
#pragma unroll
        for (int j = 0; j < 4; ++j) {
            int col = n0 + wn * 32 + j * 8 + 2 * tig;
#pragma unroll
            for (int h = 0; h < 2; ++h) {   // h=0: rows +g, c0/c1; h=1: +g+8, c2/c3
                int row = m0 + wm * 64 + i * 16 + g + h * 8;
                size_t p = (size_t)row * N + col;
                float2 cur = *(const float2*)(Bcur + p);
                float2 old = *(const float2*)(Bold + p);
                float ox = 2.0f * acc[i][j][h * 2 + 0] - 2.0f * cur.x - old.x;
                float oy = 2.0f * acc[i][j][h * 2 + 1] - 2.0f * cur.y - old.y;
                *(float2*)(Cnew + p) = make_float2(ox, oy);
                if (emit) {
                    __nv_bfloat16 hx = __float2bfloat16(ox);
                    __nv_bfloat16 hy = __float2bfloat16(oy);
                    __nv_bfloat162 hv, lv;
                    hv.x = hx;  hv.y = hy;
                    lv.x = __float2bfloat16(ox - __bfloat162float(hx));
                    lv.y = __float2bfloat16(oy - __bfloat162float(hy));
                    *(__nv_bfloat162*)(bh + p) = hv;
                    *(__nv_bfloat162*)(bl + p) = lv;
                }
            }
        }
    }
}

// ---------------------------------------------------------------------------
// out[f] = 0.5*c0[f]*T0 + sum_{k>=1} c_k[f]*T_k
// ---------------------------------------------------------------------------
__global__ __launch_bounds__(256)
void combine_kernel(float* __restrict__ out) {
    __shared__ float w[NCOEF * NF];
    if (threadIdx.x < NCOEF * NF) {
        float v = d_c[threadIdx.x];
        if (threadIdx.x < NF) v *= 0.5f;
        w[threadIdx.x] = v;
    }
    __syncthreads();

    size_t e0 = ((size_t)blockIdx.x * blockDim.x + threadIdx.x) * 4;
    if (e0 >= NN) return;

    float4 t[NCOEF];
#pragma unroll
    for (int kq = 0; kq < NCOEF; kq++)
        t[kq] = *(const float4*)(d_T + (size_t)kq * NN + e0);

#pragma unroll
    for (int f = 0; f < NF; f++) {
        float4 a = make_float4(0.f, 0.f, 0.f, 0.f);
#pragma unroll
        for (int kq = 0; kq < NCOEF; kq++) {
            float wk = w[kq * NF + f];
            a.x += wk * t[kq].x;
            a.y += wk * t[kq].y;
            a.z += wk * t[kq].z;
            a.w += wk * t[kq].w;
        }
        *(float4*)(out + (size_t)f * NN + e0) = a;
    }
}

// ---------------------------------------------------------------------------
extern "C" void kernel_launch(void* const* d_in, const int* in_sizes, int n_in,
                              void* d_out, int out_size) {
    const float* L    = (const float*)d_in[0];
    const float* taus = (const float*)d_in[1];
    // d_in[2] = order, fixed at 16 by setup_inputs (NCOEF = 17)
    float* out = (float*)d_out;

    coeff_kernel<<<1, 32>>>(taus);
    init_kernel<<<NN / 256, 256>>>(L);

    dim3 ggrid(N / 128, N / 128);   // (16, 16)
    for (int k = 2; k < NCOEF; k++)
        mma_gemm<<<ggrid, 256>>>(k);

    combine_kernel<<<NN / 4 / 256, 256>>>(out);
}

// round 8
// speedup vs baseline: 1.1272x; 1.1272x over previous
#include <cuda_runtime.h>
#include <cuda_bf16.h>
#include <cstdint>
#include <math.h>

#define N      2048
#define NN     (N * N)
#define NF     8
#define NCOEF  17          // order = 16 (fixed by setup_inputs)

// fp32 Chebyshev slices T_0..T_16 (recurrence epilogue + final combine)
__device__ float d_T[NCOEF * NN];
__device__ float d_c[NCOEF * NF];
// bf16 hi/lo split operands. A = L (row-major). B = T_j splits (row-major;
// T_j is symmetric, so row-major == its transpose). Double-buffered by j&1:
// GEMM k reads buf (k-1)&1, writes buf k&1.
__device__ __nv_bfloat16 d_Ahi[NN], d_Alo[NN];
__device__ __nv_bfloat16 d_Bhi[2][NN], d_Blo[2][NN];

// ---------------------------------------------------------------------------
// Warp-level MMA helpers (portable PTX, valid on plain sm_103 target)
// ---------------------------------------------------------------------------
__device__ __forceinline__ uint32_t smem_u32(const void* p) {
    return (uint32_t)__cvta_generic_to_shared(p);
}
__device__ __forceinline__ void ldsm_x4(uint32_t* r, uint32_t a) {
    asm volatile("ldmatrix.sync.aligned.m8n8.x4.shared.b16 {%0,%1,%2,%3}, [%4];"
                 : "=r"(r[0]), "=r"(r[1]), "=r"(r[2]), "=r"(r[3]) : "r"(a));
}
__device__ __forceinline__ void ldsm_x2(uint32_t* r, uint32_t a) {
    asm volatile("ldmatrix.sync.aligned.m8n8.x2.shared.b16 {%0,%1}, [%2];"
                 : "=r"(r[0]), "=r"(r[1]) : "r"(a));
}
__device__ __forceinline__ void mma_bf16(float* c, const uint32_t* a,
                                         const uint32_t* b) {
    asm volatile(
        "mma.sync.aligned.m16n8k16.row.col.f32.bf16.bf16.f32 "
        "{%0,%1,%2,%3}, {%4,%5,%6,%7}, {%8,%9}, {%0,%1,%2,%3};"
        : "+f"(c[0]), "+f"(c[1]), "+f"(c[2]), "+f"(c[3])
        : "r"(a[0]), "r"(a[1]), "r"(a[2]), "r"(a[3]), "r"(b[0]), "r"(b[1]));
}
__device__ __forceinline__ void cp_async16(uint32_t s, const void* g) {
    asm volatile("cp.async.cg.shared.global [%0], [%1], 16;"
                 :: "r"(s), "l"(g));
}

// ---------------------------------------------------------------------------
// Chebyshev coefficients: c = (2/Ncoef) * C @ fe    (a1 = a2 = 1)
// ---------------------------------------------------------------------------
__global__ void coeff_kernel(const float* __restrict__ taus) {
    int j = threadIdx.x;
    if (j >= NCOEF) return;
    double acc[NF];
#pragma unroll
    for (int f = 0; f < NF; f++) acc[f] = 0.0;
    for (int n = 0; n < NCOEF; n++) {
        double ang = M_PI * (n + 0.5) / NCOEF;
        double pt  = cos(ang) + 1.0;
        double Cjn = cos((double)j * ang);
#pragma unroll
        for (int f = 0; f < NF; f++)
            acc[f] += Cjn * exp(-pt * (double)taus[f]);
    }
#pragma unroll
    for (int f = 0; f < NF; f++)
        d_c[j * NF + f] = (float)(acc[f] * 2.0 / NCOEF);
}

// ---------------------------------------------------------------------------
// T0 = I, T1 = L - I (fp32); A-splits of L; B-splits of T1 into buf 1
// ---------------------------------------------------------------------------
__global__ void init_kernel(const float* __restrict__ L) {
    int idx = blockIdx.x * blockDim.x + threadIdx.x;
    if (idx >= NN) return;
    int i = idx >> 11;
    int j = idx & (N - 1);
    float e = (i == j) ? 1.0f : 0.0f;
    float v = L[idx];
    float t1 = v - e;
    d_T[idx]      = e;
    d_T[NN + idx] = t1;
    __nv_bfloat16 h = __float2bfloat16(v);
    d_Ahi[idx] = h;
    d_Alo[idx] = __float2bfloat16(v - __bfloat162float(h));
    __nv_bfloat16 h1 = __float2bfloat16(t1);
    d_Bhi[1][idx] = h1;
    d_Blo[1][idx] = __float2bfloat16(t1 - __bfloat162float(h1));
}

// ---------------------------------------------------------------------------
// HMMA GEMM: T_k = 2*(L @ T_{k-1}) - 2*T_{k-1} - T_{k-2}
// CTA 128x128, BK=32, 256 threads = 8 warps (2m x 4n), warp tile 64x32.
// bf16 split-3, fp32 accumulate. cp.async 2-stage smem pipeline.
// Epilogue emits bf16 splits of T_k.
// ---------------------------------------------------------------------------
#define BK    32
#define PADK  40                      // row stride in elements (80 B)
#define NKT   (N / BK)                // 64
#define ARR_BYTES   (128 * PADK * 2)  // 10240 B per tile array
#define STG_BYTES   (4 * ARR_BYTES)   // 40960 B per stage
#define SMEM_DYN    (2 * STG_BYTES)   // 81920 B

__global__ __launch_bounds__(256, 2)
void mma_gemm(int k) {
    extern __shared__ __align__(16) char dynsmem[];
    uint32_t sbase = smem_u32(dynsmem);

    const float* __restrict__ Bcur = d_T + (size_t)(k - 1) * NN;
    const float* __restrict__ Bold = d_T + (size_t)(k - 2) * NN;
    float* __restrict__ Cnew       = d_T + (size_t)k * NN;
    int rbuf = (k - 1) & 1, wbuf = k & 1;

    int tid  = threadIdx.x;
    int lane = tid & 31, wid = tid >> 5;
    int wm = wid & 1, wn = wid >> 1;         // warp grid 2(m) x 4(n)
    int g = lane >> 2, tig = lane & 3;
    int quad = lane >> 3, lr = lane & 7;

    int m0 = blockIdx.y * 128, n0 = blockIdx.x * 128;

    const __nv_bfloat16* gAh = d_Ahi + (size_t)m0 * N;
    const __nv_bfloat16* gAl = d_Alo + (size_t)m0 * N;
    const __nv_bfloat16* gBh = d_Bhi[rbuf] + (size_t)n0 * N;
    const __nv_bfloat16* gBl = d_Blo[rbuf] + (size_t)n0 * N;

    // per-thread cp.async source row/chunk (2 ops per array per stage)
    int ldR[2], ldC[2];
    uint32_t ldSo[2];
#pragma unroll
    for (int h = 0; h < 2; ++h) {
        int f = tid + h * 256;               // 0..511
        ldR[h] = f >> 2;
        ldC[h] = f & 3;
        ldSo[h] = (uint32_t)(ldR[h] * (PADK * 2) + ldC[h] * 16);
    }

    // ldmatrix per-thread byte offsets (within a tile array)
    uint32_t aoff[4], boff[4];
#pragma unroll
    for (int i = 0; i < 4; ++i)
        aoff[i] = (uint32_t)((wm * 64 + i * 16 + lr + (quad & 1) * 8) * (PADK * 2)
                             + (quad >> 1) * 16);
#pragma unroll
    for (int j = 0; j < 4; ++j)
        boff[j] = (uint32_t)((wn * 32 + j * 8 + lr) * (PADK * 2)
                             + ((lane >> 3) & 1) * 16);

    float acc[4][4][4];
#pragma unroll
    for (int i = 0; i < 4; ++i)
#pragma unroll
        for (int j = 0; j < 4; ++j)
#pragma unroll
            for (int c = 0; c < 4; ++c) acc[i][j][c] = 0.0f;

    // stage loader: issues 8 cp.async 16B ops + commit
    auto load_stage = [&](int kt, int st) {
        int k0 = kt * BK;
        uint32_t sb = sbase + (uint32_t)st * STG_BYTES;
#pragma unroll
        for (int h = 0; h < 2; ++h) {
            int r = ldR[h], c4 = ldC[h];
            uint32_t so = sb + ldSo[h];
            const char* pa = (const char*)(gAh + (size_t)r * N + k0) + c4 * 16;
            const char* pb = (const char*)(gAl + (size_t)r * N + k0) + c4 * 16;
            const char* pc = (const char*)(gBh + (size_t)r * N + k0) + c4 * 16;
            const char* pd = (const char*)(gBl + (size_t)r * N + k0) + c4 * 16;
            cp_async16(so,                 pa);
            cp_async16(so + ARR_BYTES,     pb);
            cp_async16(so + 2 * ARR_BYTES, pc);
            cp_async16(so + 3 * ARR_BYTES, pd);
        }
        asm volatile("cp.async.commit_group;");
    };

    load_stage(0, 0);

    for (int kt = 0; kt < NKT; ++kt) {
        int st = kt & 1;
        if (kt + 1 < NKT) {
            load_stage(kt + 1, st ^ 1);
            asm volatile("cp.async.wait_group 1;");
        } else {
            asm volatile("cp.async.wait_group 0;");
        }
        __syncthreads();

        uint32_t sb = sbase + (uint32_t)st * STG_BYTES;
        uint32_t uAhi = sb, uAlo = sb + ARR_BYTES;
        uint32_t uBhi = sb + 2 * ARR_BYTES, uBlo = sb + 3 * ARR_BYTES;

#pragma unroll
        for (int s = 0; s < 2; ++s) {       // two K=16 steps within BK=32
            uint32_t soff = s * 32;
            uint32_t bh[4][2], bl[4][2];
#pragma unroll
            for (int j = 0; j < 4; ++j) {
                ldsm_x2(bh[j], uBhi + boff[j] + soff);
                ldsm_x2(bl[j], uBlo + boff[j] + soff);
            }
#pragma unroll
            for (int i = 0; i < 4; ++i) {
                uint32_t ah[4], al[4];
                ldsm_x4(ah, uAhi + aoff[i] + soff);
                ldsm_x4(al, uAlo + aoff[i] + soff);
#pragma unroll
                for (int j = 0; j < 4; ++j) {
                    mma_bf16(acc[i][j], ah, bh[j]);
                    mma_bf16(acc[i][j], ah, bl[j]);
                    mma_bf16(acc[i][j], al, bh[j]);
                }
            }
        }
        __syncthreads();
    }

    // Epilogue: T_k = 2*acc - 2*T_{k-1} - T_{k-2}; emit bf16 splits of T_k
    bool emit = (k < NCOEF - 1);
    __nv_bfloat16* bh = d_Bhi[wbuf];
    __nv_bfloat16* bl = d_Blo[wbuf];
#pragma unroll
    for (int i = 0; i < 4; ++i) {
#pragma unroll
        for (int j = 0; j < 4; ++j) {
            int col = n0 + wn * 32 + j * 8 + 2 * tig;
#pragma unroll
            for (int h = 0; h < 2; ++h) {   // h=0: rows +g, c0/c1; h=1: +g+8, c2/c3
                int row = m0 + wm * 64 + i * 16 + g + h * 8;
                size_t p = (size_t)row * N + col;
                float2 cur = *(const float2*)(Bcur + p);
                float2 old = *(const float2*)(Bold + p);
                float ox = 2.0f * acc[i][j][h * 2 + 0] - 2.0f * cur.x - old.x;
                float oy = 2.0f * acc[i][j][h * 2 + 1] - 2.0f * cur.y - old.y;
                *(float2*)(Cnew + p) = make_float2(ox, oy);
                if (emit) {
                    __nv_bfloat16 hx = __float2bfloat16(ox);
                    __nv_bfloat16 hy = __float2bfloat16(oy);
                    __nv_bfloat162 hv, lv;
                    hv.x = hx;  hv.y = hy;
                    lv.x = __float2bfloat16(ox - __bfloat162float(hx));
                    lv.y = __float2bfloat16(oy - __bfloat162float(hy));
                    *(__nv_bfloat162*)(bh + p) = hv;
                    *(__nv_bfloat162*)(bl + p) = lv;
                }
            }
        }
    }
}

// ---------------------------------------------------------------------------
// out[f] = 0.5*c0[f]*T0 + sum_{k>=1} c_k[f]*T_k
// ---------------------------------------------------------------------------
__global__ __launch_bounds__(256)
void combine_kernel(float* __restrict__ out) {
    __shared__ float w[NCOEF * NF];
    if (threadIdx.x < NCOEF * NF) {
        float v = d_c[threadIdx.x];
        if (threadIdx.x < NF) v *= 0.5f;
        w[threadIdx.x] = v;
    }
    __syncthreads();

    size_t e0 = ((size_t)blockIdx.x * blockDim.x + threadIdx.x) * 4;
    if (e0 >= NN) return;

    float4 t[NCOEF];
#pragma unroll
    for (int kq = 0; kq < NCOEF; kq++)
        t[kq] = *(const float4*)(d_T + (size_t)kq * NN + e0);

#pragma unroll
    for (int f = 0; f < NF; f++) {
        float4 a = make_float4(0.f, 0.f, 0.f, 0.f);
#pragma unroll
        for (int kq = 0; kq < NCOEF; kq++) {
            float wk = w[kq * NF + f];
            a.x += wk * t[kq].x;
            a.y += wk * t[kq].y;
            a.z += wk * t[kq].z;
            a.w += wk * t[kq].w;
        }
        *(float4*)(out + (size_t)f * NN + e0) = a;
    }
}

// ---------------------------------------------------------------------------
extern "C" void kernel_launch(void* const* d_in, const int* in_sizes, int n_in,
                              void* d_out, int out_size) {
    const float* L    = (const float*)d_in[0];
    const float* taus = (const float*)d_in[1];
    // d_in[2] = order, fixed at 16 by setup_inputs (NCOEF = 17)
    float* out = (float*)d_out;

    // Idempotent host-side call (no static guards allowed by harness rules)
    cudaFuncSetAttribute(mma_gemm, cudaFuncAttributeMaxDynamicSharedMemorySize,
                         SMEM_DYN);

    coeff_kernel<<<1, 32>>>(taus);
    init_kernel<<<NN / 256, 256>>>(L);

    dim3 ggrid(N / 128, N / 128);   // (16, 16)
    for (int k = 2; k < NCOEF; k++)
        mma_gemm<<<ggrid, 256, SMEM_DYN>>>(k);

    combine_kernel<<<NN / 4 / 256, 256>>>(out);
}